// round 2
// baseline (speedup 1.0000x reference)
#include <cuda_runtime.h>
#include <math.h>

#define T 512
#define B 128
#define D 256
#define H 256

// Scratch for precomputed input projections, one per direction: [T*B, H]
__device__ float g_xw[2][(size_t)T * B * H];

// ---------------------------------------------------------------------------
// Kernel 1: xw[dir] = inputs @ W_xh[dir] + b[dir]
// A: [M=T*B, K=D] row-major, W: [D, H] row-major, out: [M, H]
// Tiles: BM=64 x BN=128, BK=16, 256 threads, 8x4 micro-tile per thread.
// ---------------------------------------------------------------------------
#define BM 64
#define BN 128
#define BK 16

__global__ void proj_kernel(const float* __restrict__ inp,
                            const float* __restrict__ Wf, const float* __restrict__ bfp,
                            const float* __restrict__ Wb, const float* __restrict__ bbp)
{
    const int dir = blockIdx.z;
    const float* __restrict__ Wx   = dir ? Wb : Wf;
    const float* __restrict__ bias = dir ? bbp : bfp;
    float* __restrict__ out = g_xw[dir];

    __shared__ float As[BK][BM + 4];   // [k][m], padded
    __shared__ float Bs[BK][BN];       // [k][n]

    const int m0 = blockIdx.x * BM;
    const int n0 = blockIdx.y * BN;

    const int tid = threadIdx.x;       // 0..255
    const int tx  = tid & 31;          // cols n0 + tx*4 .. +3
    const int ty  = tid >> 5;          // rows m0 + ty*8 .. +7

    // A-load mapping: one float4 per thread
    const int am = tid >> 2;           // 0..63 (row within tile)
    const int a4 = tid & 3;            // 0..3  (float4 index within 16-wide k chunk)
    // B-load mapping: two float4 per thread
    const int bn = tid & 31;           // float4 col
    const int bk = tid >> 5;           // 0..7, rows bk and bk+8

    float acc[8][4];
    #pragma unroll
    for (int r = 0; r < 8; r++)
        #pragma unroll
        for (int c = 0; c < 4; c++) acc[r][c] = 0.f;

    float bv[4];
    #pragma unroll
    for (int c = 0; c < 4; c++) bv[c] = bias[n0 + tx * 4 + c];

    for (int k0 = 0; k0 < D; k0 += BK) {
        // load A tile (64 x 16)
        {
            float4 v = *(const float4*)&inp[(size_t)(m0 + am) * D + k0 + a4 * 4];
            As[a4 * 4 + 0][am] = v.x;
            As[a4 * 4 + 1][am] = v.y;
            As[a4 * 4 + 2][am] = v.z;
            As[a4 * 4 + 3][am] = v.w;
        }
        // load B tile (16 x 128)
        {
            float4 v0 = *(const float4*)&Wx[(size_t)(k0 + bk) * H + n0 + bn * 4];
            float4 v1 = *(const float4*)&Wx[(size_t)(k0 + bk + 8) * H + n0 + bn * 4];
            *(float4*)&Bs[bk][bn * 4]     = v0;
            *(float4*)&Bs[bk + 8][bn * 4] = v1;
        }
        __syncthreads();

        #pragma unroll
        for (int kk = 0; kk < BK; kk++) {
            float4 a0 = *(const float4*)&As[kk][ty * 8];
            float4 a1 = *(const float4*)&As[kk][ty * 8 + 4];
            float4 bq = *(const float4*)&Bs[kk][tx * 4];
            float ar[8] = {a0.x, a0.y, a0.z, a0.w, a1.x, a1.y, a1.z, a1.w};
            float br[4] = {bq.x, bq.y, bq.z, bq.w};
            #pragma unroll
            for (int r = 0; r < 8; r++)
                #pragma unroll
                for (int c = 0; c < 4; c++)
                    acc[r][c] += ar[r] * br[c];
        }
        __syncthreads();
    }

    // epilogue: add bias, store float4
    #pragma unroll
    for (int r = 0; r < 8; r++) {
        float4 v = make_float4(acc[r][0] + bv[0], acc[r][1] + bv[1],
                               acc[r][2] + bv[2], acc[r][3] + bv[3]);
        *(float4*)&out[(size_t)(m0 + ty * 8 + r) * H + n0 + tx * 4] = v;
    }
}

// ---------------------------------------------------------------------------
// Kernel 2: recurrent scan, persistent blocks.
// 128 blocks: blocks [0,64) forward, [64,128) backward. Each owns 2 batch rows.
// W_hh rows k in [0, KSM) cached in SMEM (fp32); k in [KSM, H) read from L2.
// Per step: h = tanh(xw[t] + h @ W_hh); write to out; also final states.
// ---------------------------------------------------------------------------
#define KSM 224
#define SMEM_SCAN ((KSM * H + 2 * H) * 4)   // 231,424 bytes

__global__ void scan_kernel(const float* __restrict__ Whh_f,
                            const float* __restrict__ Whh_b,
                            float* __restrict__ out)
{
    extern __shared__ float sm[];
    float* W_s = sm;                 // [KSM][H]
    float* h_s = sm + KSM * H;       // [2][H]

    const int blk  = blockIdx.x;     // 0..127
    const int dir  = blk >> 6;       // 0 fwd, 1 bwd
    const int brow = (blk & 63) * 2; // batch rows brow, brow+1
    const float* __restrict__ Whh = dir ? Whh_b : Whh_f;
    const float* __restrict__ xw  = g_xw[dir];
    const int j = threadIdx.x;       // 0..255 (output column)

    // stage W into smem (once)
    for (int k = 0; k < KSM; k++)
        W_s[k * H + j] = Whh[k * H + j];
    h_s[j] = 0.f;
    h_s[H + j] = 0.f;
    __syncthreads();

    float* __restrict__ fin = out + (size_t)T * B * 2 * H;  // f_H then b_H

    int t  = dir ? (T - 1) : 0;
    const int dt = dir ? -1 : 1;
    float h0 = 0.f, h1 = 0.f;

    for (int s = 0; s < T; s++, t += dt) {
        // input projection for this step (issued early; needed at the end)
        const float* xr = xw + ((size_t)t * B + brow) * H + j;
        float acc0 = __ldg(xr);
        float acc1 = __ldg(xr + H);

        // k-tail from global (L2-resident); issued early to hide latency
        #pragma unroll
        for (int k = KSM; k < H; k++) {
            float w = __ldg(&Whh[k * H + j]);
            acc0 += h_s[k] * w;
            acc1 += h_s[H + k] * w;
        }

        // main accumulation from smem
        const float4* h40 = (const float4*)h_s;
        const float4* h41 = (const float4*)(h_s + H);
        #pragma unroll 4
        for (int k4 = 0; k4 < KSM / 4; k4++) {
            float4 a = h40[k4];
            float4 b = h41[k4];
            const float* wp = &W_s[(k4 * 4) * H + j];
            float w0 = wp[0];
            float w1 = wp[H];
            float w2 = wp[2 * H];
            float w3 = wp[3 * H];
            acc0 += a.x * w0; acc1 += b.x * w0;
            acc0 += a.y * w1; acc1 += b.y * w1;
            acc0 += a.z * w2; acc1 += b.z * w2;
            acc0 += a.w * w3; acc1 += b.w * w3;
        }

        h0 = tanhf(acc0);
        h1 = tanhf(acc1);

        // write outputs: out[t][b][dir*H + j]
        size_t ob = ((size_t)t * B + brow) * (2 * H) + (size_t)dir * H + j;
        out[ob]         = h0;
        out[ob + 2 * H] = h1;

        // publish new h
        __syncthreads();
        h_s[j]     = h0;
        h_s[H + j] = h1;
        __syncthreads();
    }

    // final states: forward -> fin[0 : B*H), backward -> fin[B*H : 2*B*H)
    size_t fb = (size_t)dir * B * H + (size_t)brow * H + j;
    fin[fb]     = h0;
    fin[fb + H] = h1;
}

// ---------------------------------------------------------------------------
extern "C" void kernel_launch(void* const* d_in, const int* in_sizes, int n_in,
                              void* d_out, int out_size)
{
    const float* inp = (const float*)d_in[0];
    const float* Wxf = (const float*)d_in[1];
    const float* Whf = (const float*)d_in[2];
    const float* bf  = (const float*)d_in[3];
    const float* Wxb = (const float*)d_in[4];
    const float* Whb = (const float*)d_in[5];
    const float* bb  = (const float*)d_in[6];
    float* out = (float*)d_out;

    dim3 g1(T * B / BM, H / BN, 2);
    proj_kernel<<<g1, 256>>>(inp, Wxf, bf, Wxb, bb);

    cudaFuncSetAttribute(scan_kernel,
                         cudaFuncAttributeMaxDynamicSharedMemorySize, SMEM_SCAN);
    scan_kernel<<<128, 256, SMEM_SCAN>>>(Whf, Whb, out);
}

// round 3
// speedup vs baseline: 1.2174x; 1.2174x over previous
#include <cuda_runtime.h>
#include <math.h>

#define T 512
#define B 128
#define D 256
#define H 256

// Scratch for precomputed input projections, one per direction: [T*B, H]
__device__ float g_xw[2][(size_t)T * B * H];

typedef unsigned long long u64;

__device__ __forceinline__ u64 pk2(float lo, float hi) {
    u64 r; asm("mov.b64 %0, {%1, %2};" : "=l"(r) : "f"(lo), "f"(hi)); return r;
}
__device__ __forceinline__ void upk2(float& lo, float& hi, u64 v) {
    asm("mov.b64 {%0, %1}, %2;" : "=f"(lo), "=f"(hi) : "l"(v));
}
__device__ __forceinline__ void ffma2(u64& acc, u64 a, u64 b) {
    asm("fma.rn.f32x2 %0, %1, %2, %3;" : "=l"(acc) : "l"(a), "l"(b), "l"(acc));
}
__device__ __forceinline__ float tanh_fast(float x) {
    float y; asm("tanh.approx.f32 %0, %1;" : "=f"(y) : "f"(x)); return y;
}

// ---------------------------------------------------------------------------
// Kernel 1: xw[dir] = inputs @ W_xh[dir] + b[dir]   (FFMA2 inner product)
// ---------------------------------------------------------------------------
#define BM 64
#define BN 128
#define BK 16

__global__ __launch_bounds__(256) void proj_kernel(
    const float* __restrict__ inp,
    const float* __restrict__ Wf, const float* __restrict__ bfp,
    const float* __restrict__ Wb, const float* __restrict__ bbp)
{
    const int dir = blockIdx.z;
    const float* __restrict__ Wx   = dir ? Wb : Wf;
    const float* __restrict__ bias = dir ? bbp : bfp;
    float* __restrict__ out = g_xw[dir];

    __shared__ float As[BK][BM + 4];   // [k][m]
    __shared__ float Bs[BK][BN];       // [k][n]

    const int m0 = blockIdx.x * BM;
    const int n0 = blockIdx.y * BN;

    const int tid = threadIdx.x;
    const int tx  = tid & 31;          // cols n0 + tx*4 .. +3
    const int ty  = tid >> 5;          // rows m0 + ty*8 .. +7

    const int am = tid >> 2;
    const int a4 = tid & 3;
    const int bn = tid & 31;
    const int bk = tid >> 5;

    // acc2[p][c]: 64-bit pair = (row 2p, row 2p+1) for column c
    u64 acc2[4][4];
    #pragma unroll
    for (int p = 0; p < 4; p++)
        #pragma unroll
        for (int c = 0; c < 4; c++) acc2[p][c] = 0ull;

    float bv[4];
    #pragma unroll
    for (int c = 0; c < 4; c++) bv[c] = bias[n0 + tx * 4 + c];

    for (int k0 = 0; k0 < D; k0 += BK) {
        {
            float4 v = *(const float4*)&inp[(size_t)(m0 + am) * D + k0 + a4 * 4];
            As[a4 * 4 + 0][am] = v.x;
            As[a4 * 4 + 1][am] = v.y;
            As[a4 * 4 + 2][am] = v.z;
            As[a4 * 4 + 3][am] = v.w;
        }
        {
            float4 v0 = *(const float4*)&Wx[(size_t)(k0 + bk) * H + n0 + bn * 4];
            float4 v1 = *(const float4*)&Wx[(size_t)(k0 + bk + 8) * H + n0 + bn * 4];
            *(float4*)&Bs[bk][bn * 4]     = v0;
            *(float4*)&Bs[bk + 8][bn * 4] = v1;
        }
        __syncthreads();

        #pragma unroll
        for (int kk = 0; kk < BK; kk++) {
            // rows come out as natural 64-bit pairs (r0,r1),(r2,r3),(r4,r5),(r6,r7)
            ulonglong2 ap0 = *(const ulonglong2*)&As[kk][ty * 8];
            ulonglong2 ap1 = *(const ulonglong2*)&As[kk][ty * 8 + 4];
            float4 bq = *(const float4*)&Bs[kk][tx * 4];
            u64 bb[4];
            bb[0] = pk2(bq.x, bq.x);
            bb[1] = pk2(bq.y, bq.y);
            bb[2] = pk2(bq.z, bq.z);
            bb[3] = pk2(bq.w, bq.w);
            #pragma unroll
            for (int c = 0; c < 4; c++) {
                ffma2(acc2[0][c], ap0.x, bb[c]);
                ffma2(acc2[1][c], ap0.y, bb[c]);
                ffma2(acc2[2][c], ap1.x, bb[c]);
                ffma2(acc2[3][c], ap1.y, bb[c]);
            }
        }
        __syncthreads();
    }

    // epilogue: unpack, add bias, store one float4 per row
    #pragma unroll
    for (int p = 0; p < 4; p++) {
        float lo[4], hi[4];
        #pragma unroll
        for (int c = 0; c < 4; c++) upk2(lo[c], hi[c], acc2[p][c]);
        float4 v0 = make_float4(lo[0] + bv[0], lo[1] + bv[1], lo[2] + bv[2], lo[3] + bv[3]);
        float4 v1 = make_float4(hi[0] + bv[0], hi[1] + bv[1], hi[2] + bv[2], hi[3] + bv[3]);
        *(float4*)&out[(size_t)(m0 + ty * 8 + 2 * p)     * H + n0 + tx * 4] = v0;
        *(float4*)&out[(size_t)(m0 + ty * 8 + 2 * p + 1) * H + n0 + tx * 4] = v1;
    }
}

// ---------------------------------------------------------------------------
// Kernel 2: recurrent scan, persistent blocks (128 blocks, 1/SM).
// W rows [0,KSM) live in smem in PACKED layout W_p[k/4][j][4] so each thread
// reads one conflict-free LDS.128 per 4 k. Tail rows [KSM,H) live in REGISTERS
// (packed as f32x2 pairs). All inner math is fma.rn.f32x2.
// ---------------------------------------------------------------------------
#define KSM 224
#define NK4 (KSM / 4)                       // 56
#define NT  (H - KSM)                       // 32 tail rows
#define SMEM_SCAN ((KSM * H + 2 * H) * 4)   // 231,424 bytes

__global__ __launch_bounds__(256) void scan_kernel(
    const float* __restrict__ Whh_f,
    const float* __restrict__ Whh_b,
    float* __restrict__ out)
{
    extern __shared__ float sm[];
    float* W_p = sm;                  // packed [NK4][H][4]
    float* h0s = sm + KSM * H;        // [H]
    float* h1s = h0s + H;             // [H]

    const int blk  = blockIdx.x;      // 0..127
    const int dir  = blk >> 6;
    const int brow = (blk & 63) * 2;
    const float* __restrict__ Whh = dir ? Whh_b : Whh_f;
    const float* __restrict__ xw  = g_xw[dir];
    const int j = threadIdx.x;        // 0..255

    // stage W rows [0,KSM) into packed smem
    for (int k = 0; k < KSM; k++)
        W_p[(k >> 2) * (H * 4) + j * 4 + (k & 3)] = Whh[k * H + j];

    // tail W rows into registers, packed as f32x2 pairs
    u64 wtp[NT / 2];
    #pragma unroll
    for (int i = 0; i < NT / 2; i++) {
        float w0 = Whh[(KSM + 2 * i)     * H + j];
        float w1 = Whh[(KSM + 2 * i + 1) * H + j];
        wtp[i] = pk2(w0, w1);
    }

    h0s[j] = 0.f;
    h1s[j] = 0.f;
    __syncthreads();

    float* __restrict__ fin = out + (size_t)T * B * 2 * H;

    int t  = dir ? (T - 1) : 0;
    const int dt = dir ? -1 : 1;
    float h0 = 0.f, h1 = 0.f;

    for (int s = 0; s < T; s++, t += dt) {
        const float* xr = xw + ((size_t)t * B + brow) * H + j;
        float x0 = __ldg(xr);
        float x1 = __ldg(xr + H);

        // acc[row][phase] : 8 independent f32x2 accumulator chains
        u64 acc[2][4];
        #pragma unroll
        for (int r = 0; r < 2; r++)
            #pragma unroll
            for (int p = 0; p < 4; p++) acc[r][p] = 0ull;

        // tail (W in registers, h broadcast from smem)
        #pragma unroll
        for (int i = 0; i < NT / 4; i++) {          // 8 iters, 4 k each
            ulonglong2 a = *(const ulonglong2*)&h0s[KSM + 4 * i];
            ulonglong2 b = *(const ulonglong2*)&h1s[KSM + 4 * i];
            int p0 = (i & 1) * 2;
            ffma2(acc[0][p0],     a.x, wtp[2 * i]);
            ffma2(acc[0][p0 + 1], a.y, wtp[2 * i + 1]);
            ffma2(acc[1][p0],     b.x, wtp[2 * i]);
            ffma2(acc[1][p0 + 1], b.y, wtp[2 * i + 1]);
        }

        // main body from packed smem
        #pragma unroll
        for (int k4 = 0; k4 < NK4; k4++) {
            ulonglong2 w = *(const ulonglong2*)&W_p[(k4 * H + j) * 4];
            ulonglong2 a = *(const ulonglong2*)&h0s[k4 * 4];
            ulonglong2 b = *(const ulonglong2*)&h1s[k4 * 4];
            int p0 = (k4 & 1) * 2;
            ffma2(acc[0][p0],     a.x, w.x);
            ffma2(acc[0][p0 + 1], a.y, w.y);
            ffma2(acc[1][p0],     b.x, w.x);
            ffma2(acc[1][p0 + 1], b.y, w.y);
        }

        // reduce pairs
        float s00, s01, s0 = x0;
        float s10, s11, s1 = x1;
        #pragma unroll
        for (int p = 0; p < 4; p++) {
            upk2(s00, s01, acc[0][p]); s0 += s00 + s01;
            upk2(s10, s11, acc[1][p]); s1 += s10 + s11;
        }

        h0 = tanh_fast(s0);
        h1 = tanh_fast(s1);

        size_t ob = ((size_t)t * B + brow) * (2 * H) + (size_t)dir * H + j;
        out[ob]         = h0;
        out[ob + 2 * H] = h1;

        __syncthreads();
        h0s[j] = h0;
        h1s[j] = h1;
        __syncthreads();
    }

    size_t fb = (size_t)dir * B * H + (size_t)brow * H + j;
    fin[fb]     = h0;
    fin[fb + H] = h1;
}

// ---------------------------------------------------------------------------
extern "C" void kernel_launch(void* const* d_in, const int* in_sizes, int n_in,
                              void* d_out, int out_size)
{
    const float* inp = (const float*)d_in[0];
    const float* Wxf = (const float*)d_in[1];
    const float* Whf = (const float*)d_in[2];
    const float* bf  = (const float*)d_in[3];
    const float* Wxb = (const float*)d_in[4];
    const float* Whb = (const float*)d_in[5];
    const float* bb  = (const float*)d_in[6];
    float* out = (float*)d_out;

    dim3 g1(T * B / BM, H / BN, 2);
    proj_kernel<<<g1, 256>>>(inp, Wxf, bf, Wxb, bb);

    cudaFuncSetAttribute(scan_kernel,
                         cudaFuncAttributeMaxDynamicSharedMemorySize, SMEM_SCAN);
    scan_kernel<<<128, 256, SMEM_SCAN>>>(Whf, Whb, out);
}

// round 5
// speedup vs baseline: 2.1548x; 1.7700x over previous
#include <cuda_runtime.h>
#include <cuda_bf16.h>
#include <math.h>

#define T 512
#define B 128
#define D 256
#define H 256

// Scratch for precomputed input projections, one per direction: [T*B, H]
__device__ float g_xw[2][(size_t)T * B * H];

typedef unsigned long long u64;
typedef unsigned int u32;

__device__ __forceinline__ u64 pk2(float lo, float hi) {
    u64 r; asm("mov.b64 %0, {%1, %2};" : "=l"(r) : "f"(lo), "f"(hi)); return r;
}
__device__ __forceinline__ void upk2(float& lo, float& hi, u64 v) {
    asm("mov.b64 {%0, %1}, %2;" : "=f"(lo), "=f"(hi) : "l"(v));
}
__device__ __forceinline__ void ffma2(u64& acc, u64 a, u64 b) {
    asm("fma.rn.f32x2 %0, %1, %2, %3;" : "=l"(acc) : "l"(a), "l"(b), "l"(acc));
}
__device__ __forceinline__ float tanh_fast(float x) {
    float y; asm("tanh.approx.f32 %0, %1;" : "=f"(y) : "f"(x)); return y;
}
// word = (bf16 w_k in low 16, bf16 w_{k+1} in high 16)
// -> u64 fp32 pair (w_k, w_{k+1}); bf16->fp32 is exact (prefix of fp32).
__device__ __forceinline__ u64 bfpair(u32 w) {
    u64 r;
    asm("{ .reg .b32 lo, hi;\n"
        "  shl.b32 lo, %1, 16;\n"
        "  and.b32 hi, %1, 0xffff0000;\n"
        "  mov.b64 %0, {lo, hi}; }" : "=l"(r) : "r"(w));
    return r;
}

// ---------------------------------------------------------------------------
// Kernel 1: xw[dir] = inputs @ W_xh[dir] + b[dir]   (FFMA2 inner product)
// ---------------------------------------------------------------------------
#define BM 64
#define BN 128
#define BK 16

__global__ __launch_bounds__(256) void proj_kernel(
    const float* __restrict__ inp,
    const float* __restrict__ Wf, const float* __restrict__ bfp,
    const float* __restrict__ Wb, const float* __restrict__ bbp)
{
    const int dir = blockIdx.z;
    const float* __restrict__ Wx   = dir ? Wb : Wf;
    const float* __restrict__ bias = dir ? bbp : bfp;
    float* __restrict__ out = g_xw[dir];

    __shared__ float As[BK][BM + 4];
    __shared__ float Bs[BK][BN];

    const int m0 = blockIdx.x * BM;
    const int n0 = blockIdx.y * BN;

    const int tid = threadIdx.x;
    const int tx  = tid & 31;
    const int ty  = tid >> 5;

    const int am = tid >> 2;
    const int a4 = tid & 3;
    const int bn = tid & 31;
    const int bk = tid >> 5;

    u64 acc2[4][4];
    #pragma unroll
    for (int p = 0; p < 4; p++)
        #pragma unroll
        for (int c = 0; c < 4; c++) acc2[p][c] = 0ull;

    float bv[4];
    #pragma unroll
    for (int c = 0; c < 4; c++) bv[c] = bias[n0 + tx * 4 + c];

    for (int k0 = 0; k0 < D; k0 += BK) {
        {
            float4 v = *(const float4*)&inp[(size_t)(m0 + am) * D + k0 + a4 * 4];
            As[a4 * 4 + 0][am] = v.x;
            As[a4 * 4 + 1][am] = v.y;
            As[a4 * 4 + 2][am] = v.z;
            As[a4 * 4 + 3][am] = v.w;
        }
        {
            float4 v0 = *(const float4*)&Wx[(size_t)(k0 + bk) * H + n0 + bn * 4];
            float4 v1 = *(const float4*)&Wx[(size_t)(k0 + bk + 8) * H + n0 + bn * 4];
            *(float4*)&Bs[bk][bn * 4]     = v0;
            *(float4*)&Bs[bk + 8][bn * 4] = v1;
        }
        __syncthreads();

        #pragma unroll
        for (int kk = 0; kk < BK; kk++) {
            ulonglong2 ap0 = *(const ulonglong2*)&As[kk][ty * 8];
            ulonglong2 ap1 = *(const ulonglong2*)&As[kk][ty * 8 + 4];
            float4 bq = *(const float4*)&Bs[kk][tx * 4];
            u64 bb[4];
            bb[0] = pk2(bq.x, bq.x);
            bb[1] = pk2(bq.y, bq.y);
            bb[2] = pk2(bq.z, bq.z);
            bb[3] = pk2(bq.w, bq.w);
            #pragma unroll
            for (int c = 0; c < 4; c++) {
                ffma2(acc2[0][c], ap0.x, bb[c]);
                ffma2(acc2[1][c], ap0.y, bb[c]);
                ffma2(acc2[2][c], ap1.x, bb[c]);
                ffma2(acc2[3][c], ap1.y, bb[c]);
            }
        }
        __syncthreads();
    }

    #pragma unroll
    for (int p = 0; p < 4; p++) {
        float lo[4], hi[4];
        #pragma unroll
        for (int c = 0; c < 4; c++) upk2(lo[c], hi[c], acc2[p][c]);
        float4 v0 = make_float4(lo[0] + bv[0], lo[1] + bv[1], lo[2] + bv[2], lo[3] + bv[3]);
        float4 v1 = make_float4(hi[0] + bv[0], hi[1] + bv[1], hi[2] + bv[2], hi[3] + bv[3]);
        *(float4*)&out[(size_t)(m0 + ty * 8 + 2 * p)     * H + n0 + tx * 4] = v0;
        *(float4*)&out[(size_t)(m0 + ty * 8 + 2 * p + 1) * H + n0 + tx * 4] = v1;
    }
}

// ---------------------------------------------------------------------------
// Kernel 2: recurrent scan, persistent blocks (128 blocks, 1/SM, 256 thr).
// W_hh lives in smem as bf16, packed [k/8][j][8] so thread j reads one
// conflict-free LDS.128 per 8 k. h is fp32, double-buffered -> one barrier
// per step. All math fp32 via fma.rn.f32x2 (bf16 expanded exactly by <<16).
// ---------------------------------------------------------------------------
#define NK8 (H / 8)                           // 32
#define SMEM_SCAN (H * H * 2 + 2 * 2 * H * 4) // 131072 + 4096 bytes

__global__ __launch_bounds__(256) void scan_kernel(
    const float* __restrict__ Whh_f,
    const float* __restrict__ Whh_b,
    float* __restrict__ out)
{
    extern __shared__ char smraw[];
    uint4* Wp4  = (uint4*)smraw;                       // [NK8][H] uint4 (8 bf16)
    float* hbuf = (float*)(smraw + H * H * 2);         // [2][2][H]

    const int blk  = blockIdx.x;      // 0..127
    const int dir  = blk >> 6;
    const int brow = (blk & 63) * 2;
    const float* __restrict__ Whh = dir ? Whh_b : Whh_f;
    const float* __restrict__ xw  = g_xw[dir];
    const int j = threadIdx.x;        // 0..255 (output column)

    // ---- stage W column j into packed bf16 smem (explicit pack: lo=w_k, hi=w_{k+1})
    for (int k8 = 0; k8 < NK8; k8++) {
        u32 wrd[4];
        #pragma unroll
        for (int q = 0; q < 4; q++) {
            float w0 = Whh[(k8 * 8 + 2 * q)     * H + j];
            float w1 = Whh[(k8 * 8 + 2 * q + 1) * H + j];
            u32 b0 = (u32)__bfloat16_as_ushort(__float2bfloat16(w0));
            u32 b1 = (u32)__bfloat16_as_ushort(__float2bfloat16(w1));
            wrd[q] = (b1 << 16) | b0;
        }
        Wp4[k8 * H + j] = make_uint4(wrd[0], wrd[1], wrd[2], wrd[3]);
    }
    // zero initial h (read buffer 0)
    hbuf[j] = 0.f;          // buf0 row0
    hbuf[H + j] = 0.f;      // buf0 row1
    __syncthreads();

    float* __restrict__ fin = out + (size_t)T * B * 2 * H;

    int t  = dir ? (T - 1) : 0;
    const int dt = dir ? -1 : 1;
    int p = 0;
    float h0 = 0.f, h1 = 0.f;

    // prefetch x for step 0
    const float* xr = xw + ((size_t)t * B + brow) * H + j;
    float x0 = __ldg(xr);
    float x1 = __ldg(xr + H);

    for (int s = 0; s < T; s++) {
        // prefetch x for next step
        float xn0 = 0.f, xn1 = 0.f;
        if (s + 1 < T) {
            const float* xr2 = xw + ((size_t)(t + dt) * B + brow) * H + j;
            xn0 = __ldg(xr2);
            xn1 = __ldg(xr2 + H);
        }

        const float* hr0 = hbuf + p * (2 * H);
        const float* hr1 = hr0 + H;

        u64 acc[2][4];
        #pragma unroll
        for (int r = 0; r < 2; r++)
            #pragma unroll
            for (int q = 0; q < 4; q++) acc[r][q] = 0ull;

        #pragma unroll
        for (int k8 = 0; k8 < NK8; k8++) {
            uint4 w = Wp4[k8 * H + j];
            ulonglong2 a0 = *(const ulonglong2*)&hr0[k8 * 8];
            ulonglong2 a1 = *(const ulonglong2*)&hr0[k8 * 8 + 4];
            ulonglong2 b0 = *(const ulonglong2*)&hr1[k8 * 8];
            ulonglong2 b1 = *(const ulonglong2*)&hr1[k8 * 8 + 4];
            u64 w01 = bfpair(w.x);
            u64 w23 = bfpair(w.y);
            u64 w45 = bfpair(w.z);
            u64 w67 = bfpair(w.w);
            ffma2(acc[0][0], a0.x, w01);
            ffma2(acc[0][1], a0.y, w23);
            ffma2(acc[0][2], a1.x, w45);
            ffma2(acc[0][3], a1.y, w67);
            ffma2(acc[1][0], b0.x, w01);
            ffma2(acc[1][1], b0.y, w23);
            ffma2(acc[1][2], b1.x, w45);
            ffma2(acc[1][3], b1.y, w67);
        }

        float s00, s01, s0 = x0;
        float s10, s11, s1 = x1;
        #pragma unroll
        for (int q = 0; q < 4; q++) {
            upk2(s00, s01, acc[0][q]); s0 += s00 + s01;
            upk2(s10, s11, acc[1][q]); s1 += s10 + s11;
        }

        h0 = tanh_fast(s0);
        h1 = tanh_fast(s1);

        // publish new h into the other buffer
        float* hw = hbuf + (p ^ 1) * (2 * H);
        hw[j]     = h0;
        hw[H + j] = h1;

        // write outputs
        size_t ob = ((size_t)t * B + brow) * (2 * H) + (size_t)dir * H + j;
        out[ob]         = h0;
        out[ob + 2 * H] = h1;

        __syncthreads();
        p ^= 1;
        t += dt;
        x0 = xn0;
        x1 = xn1;
    }

    size_t fb = (size_t)dir * B * H + (size_t)brow * H + j;
    fin[fb]     = h0;
    fin[fb + H] = h1;
}

// ---------------------------------------------------------------------------
extern "C" void kernel_launch(void* const* d_in, const int* in_sizes, int n_in,
                              void* d_out, int out_size)
{
    const float* inp = (const float*)d_in[0];
    const float* Wxf = (const float*)d_in[1];
    const float* Whf = (const float*)d_in[2];
    const float* bf  = (const float*)d_in[3];
    const float* Wxb = (const float*)d_in[4];
    const float* Whb = (const float*)d_in[5];
    const float* bb  = (const float*)d_in[6];
    float* out = (float*)d_out;

    dim3 g1(T * B / BM, H / BN, 2);
    proj_kernel<<<g1, 256>>>(inp, Wxf, bf, Wxb, bb);

    cudaFuncSetAttribute(scan_kernel,
                         cudaFuncAttributeMaxDynamicSharedMemorySize, SMEM_SCAN);
    scan_kernel<<<128, 256, SMEM_SCAN>>>(Whf, Whb, out);
}

// round 7
// speedup vs baseline: 2.8507x; 1.3229x over previous
#include <cuda_runtime.h>
#include <cuda_bf16.h>
#include <math.h>

#define T 512
#define B 128
#define D 256
#define H 256

// Scratch for precomputed input projections, one per direction: [T*B, H]
__device__ float g_xw[2][(size_t)T * B * H];

typedef unsigned long long u64;
typedef unsigned int u32;

__device__ __forceinline__ u64 pk2(float lo, float hi) {
    u64 r; asm("mov.b64 %0, {%1, %2};" : "=l"(r) : "f"(lo), "f"(hi)); return r;
}
__device__ __forceinline__ void upk2(float& lo, float& hi, u64 v) {
    asm("mov.b64 {%0, %1}, %2;" : "=f"(lo), "=f"(hi) : "l"(v));
}
__device__ __forceinline__ void ffma2(u64& acc, u64 a, u64 b) {
    asm("fma.rn.f32x2 %0, %1, %2, %3;" : "=l"(acc) : "l"(a), "l"(b), "l"(acc));
}
__device__ __forceinline__ float tanh_fast(float x) {
    float y; asm("tanh.approx.f32 %0, %1;" : "=f"(y) : "f"(x)); return y;
}
// word = (bf16 w_k in low 16, bf16 w_{k+1} in high 16)
// -> u64 fp32 pair (w_k, w_{k+1}); bf16->fp32 expansion is exact.
__device__ __forceinline__ u64 bfpair(u32 w) {
    u64 r;
    asm("{ .reg .b32 lo, hi;\n"
        "  shl.b32 lo, %1, 16;\n"
        "  and.b32 hi, %1, 0xffff0000;\n"
        "  mov.b64 %0, {lo, hi}; }" : "=l"(r) : "r"(w));
    return r;
}

// ---------------------------------------------------------------------------
// Kernel 1: xw[dir] = inputs @ W_xh[dir] + b[dir]   (FFMA2 inner product)
// ---------------------------------------------------------------------------
#define BM 64
#define BN 128
#define BK 16

__global__ __launch_bounds__(256) void proj_kernel(
    const float* __restrict__ inp,
    const float* __restrict__ Wf, const float* __restrict__ bfp,
    const float* __restrict__ Wb, const float* __restrict__ bbp)
{
    const int dir = blockIdx.z;
    const float* __restrict__ Wx   = dir ? Wb : Wf;
    const float* __restrict__ bias = dir ? bbp : bfp;
    float* __restrict__ out = g_xw[dir];

    __shared__ float As[BK][BM + 4];
    __shared__ float Bs[BK][BN];

    const int m0 = blockIdx.x * BM;
    const int n0 = blockIdx.y * BN;

    const int tid = threadIdx.x;
    const int tx  = tid & 31;
    const int ty  = tid >> 5;

    const int am = tid >> 2;
    const int a4 = tid & 3;
    const int bn = tid & 31;
    const int bk = tid >> 5;

    u64 acc2[4][4];
    #pragma unroll
    for (int p = 0; p < 4; p++)
        #pragma unroll
        for (int c = 0; c < 4; c++) acc2[p][c] = 0ull;

    float bv[4];
    #pragma unroll
    for (int c = 0; c < 4; c++) bv[c] = bias[n0 + tx * 4 + c];

    for (int k0 = 0; k0 < D; k0 += BK) {
        {
            float4 v = *(const float4*)&inp[(size_t)(m0 + am) * D + k0 + a4 * 4];
            As[a4 * 4 + 0][am] = v.x;
            As[a4 * 4 + 1][am] = v.y;
            As[a4 * 4 + 2][am] = v.z;
            As[a4 * 4 + 3][am] = v.w;
        }
        {
            float4 v0 = *(const float4*)&Wx[(size_t)(k0 + bk) * H + n0 + bn * 4];
            float4 v1 = *(const float4*)&Wx[(size_t)(k0 + bk + 8) * H + n0 + bn * 4];
            *(float4*)&Bs[bk][bn * 4]     = v0;
            *(float4*)&Bs[bk + 8][bn * 4] = v1;
        }
        __syncthreads();

        #pragma unroll
        for (int kk = 0; kk < BK; kk++) {
            ulonglong2 ap0 = *(const ulonglong2*)&As[kk][ty * 8];
            ulonglong2 ap1 = *(const ulonglong2*)&As[kk][ty * 8 + 4];
            float4 bq = *(const float4*)&Bs[kk][tx * 4];
            u64 bb[4];
            bb[0] = pk2(bq.x, bq.x);
            bb[1] = pk2(bq.y, bq.y);
            bb[2] = pk2(bq.z, bq.z);
            bb[3] = pk2(bq.w, bq.w);
            #pragma unroll
            for (int c = 0; c < 4; c++) {
                ffma2(acc2[0][c], ap0.x, bb[c]);
                ffma2(acc2[1][c], ap0.y, bb[c]);
                ffma2(acc2[2][c], ap1.x, bb[c]);
                ffma2(acc2[3][c], ap1.y, bb[c]);
            }
        }
        __syncthreads();
    }

    #pragma unroll
    for (int p = 0; p < 4; p++) {
        float lo[4], hi[4];
        #pragma unroll
        for (int c = 0; c < 4; c++) upk2(lo[c], hi[c], acc2[p][c]);
        float4 v0 = make_float4(lo[0] + bv[0], lo[1] + bv[1], lo[2] + bv[2], lo[3] + bv[3]);
        float4 v1 = make_float4(hi[0] + bv[0], hi[1] + bv[1], hi[2] + bv[2], hi[3] + bv[3]);
        *(float4*)&out[(size_t)(m0 + ty * 8 + 2 * p)     * H + n0 + tx * 4] = v0;
        *(float4*)&out[(size_t)(m0 + ty * 8 + 2 * p + 1) * H + n0 + tx * 4] = v1;
    }
}

// ---------------------------------------------------------------------------
// Kernel 2: recurrent scan, persistent blocks (128 blocks, 1/SM, 256 thr).
// Thread j owns output column j and holds the ENTIRE bf16 column of W_hh in
// 128 registers (32 x uint4), loaded once. Per step it reads only the shared
// h vectors (broadcast LDS.128) from a double-buffered 4KB smem region.
// All math fp32 via fma.rn.f32x2 (bf16 weights expanded exactly by <<16).
// ---------------------------------------------------------------------------
#define NK8 (H / 8)                 // 32
#define SMEM_SCAN (2 * 2 * H * 4)   // 4096 bytes: [phase][row][H]

__global__ __launch_bounds__(256, 1) void scan_kernel(
    const float* __restrict__ Whh_f,
    const float* __restrict__ Whh_b,
    float* __restrict__ out)
{
    __shared__ float hbuf[2 * 2 * H];

    const int blk  = blockIdx.x;      // 0..127
    const int dir  = blk >> 6;
    const int brow = (blk & 63) * 2;
    const float* __restrict__ Whh = dir ? Whh_b : Whh_f;
    const float* __restrict__ xw  = g_xw[dir];
    const int j = threadIdx.x;        // 0..255 (output column)

    // ---- load W column j into registers, packed bf16 (lo=w_k, hi=w_{k+1})
    uint4 wreg[NK8];
    #pragma unroll
    for (int k8 = 0; k8 < NK8; k8++) {
        u32 wrd[4];
        #pragma unroll
        for (int q = 0; q < 4; q++) {
            float w0 = Whh[(k8 * 8 + 2 * q)     * H + j];
            float w1 = Whh[(k8 * 8 + 2 * q + 1) * H + j];
            u32 b0 = (u32)__bfloat16_as_ushort(__float2bfloat16(w0));
            u32 b1 = (u32)__bfloat16_as_ushort(__float2bfloat16(w1));
            wrd[q] = (b1 << 16) | b0;
        }
        wreg[k8] = make_uint4(wrd[0], wrd[1], wrd[2], wrd[3]);
    }

    hbuf[j] = 0.f;          // buf0 row0
    hbuf[H + j] = 0.f;      // buf0 row1
    __syncthreads();

    float* __restrict__ fin = out + (size_t)T * B * 2 * H;

    int t  = dir ? (T - 1) : 0;
    const int dt = dir ? -1 : 1;
    int p = 0;
    float h0 = 0.f, h1 = 0.f;

    // prefetch x for step 0
    const float* xr = xw + ((size_t)t * B + brow) * H + j;
    float x0 = __ldg(xr);
    float x1 = __ldg(xr + H);

    for (int s = 0; s < T; s++) {
        // prefetch x for next step
        float xn0 = 0.f, xn1 = 0.f;
        if (s + 1 < T) {
            const float* xr2 = xw + ((size_t)(t + dt) * B + brow) * H + j;
            xn0 = __ldg(xr2);
            xn1 = __ldg(xr2 + H);
        }

        const float* hr0 = hbuf + p * (2 * H);
        const float* hr1 = hr0 + H;

        u64 acc[2][4];
        #pragma unroll
        for (int r = 0; r < 2; r++)
            #pragma unroll
            for (int q = 0; q < 4; q++) acc[r][q] = 0ull;

        #pragma unroll
        for (int k8 = 0; k8 < NK8; k8++) {
            uint4 w = wreg[k8];
            ulonglong2 a0 = *(const ulonglong2*)&hr0[k8 * 8];
            ulonglong2 a1 = *(const ulonglong2*)&hr0[k8 * 8 + 4];
            ulonglong2 b0 = *(const ulonglong2*)&hr1[k8 * 8];
            ulonglong2 b1 = *(const ulonglong2*)&hr1[k8 * 8 + 4];
            u64 w01 = bfpair(w.x);
            u64 w23 = bfpair(w.y);
            u64 w45 = bfpair(w.z);
            u64 w67 = bfpair(w.w);
            ffma2(acc[0][0], a0.x, w01);
            ffma2(acc[0][1], a0.y, w23);
            ffma2(acc[0][2], a1.x, w45);
            ffma2(acc[0][3], a1.y, w67);
            ffma2(acc[1][0], b0.x, w01);
            ffma2(acc[1][1], b0.y, w23);
            ffma2(acc[1][2], b1.x, w45);
            ffma2(acc[1][3], b1.y, w67);
        }

        float s00, s01, s0 = x0;
        float s10, s11, s1 = x1;
        #pragma unroll
        for (int q = 0; q < 4; q++) {
            upk2(s00, s01, acc[0][q]); s0 += s00 + s01;
            upk2(s10, s11, acc[1][q]); s1 += s10 + s11;
        }

        h0 = tanh_fast(s0);
        h1 = tanh_fast(s1);

        // publish new h into the other buffer
        float* hw = hbuf + (p ^ 1) * (2 * H);
        hw[j]     = h0;
        hw[H + j] = h1;

        // write outputs
        size_t ob = ((size_t)t * B + brow) * (2 * H) + (size_t)dir * H + j;
        out[ob]         = h0;
        out[ob + 2 * H] = h1;

        __syncthreads();
        p ^= 1;
        t += dt;
        x0 = xn0;
        x1 = xn1;
    }

    size_t fb = (size_t)dir * B * H + (size_t)brow * H + j;
    fin[fb]     = h0;
    fin[fb + H] = h1;
}

// ---------------------------------------------------------------------------
extern "C" void kernel_launch(void* const* d_in, const int* in_sizes, int n_in,
                              void* d_out, int out_size)
{
    const float* inp = (const float*)d_in[0];
    const float* Wxf = (const float*)d_in[1];
    const float* Whf = (const float*)d_in[2];
    const float* bf  = (const float*)d_in[3];
    const float* Wxb = (const float*)d_in[4];
    const float* Whb = (const float*)d_in[5];
    const float* bb  = (const float*)d_in[6];
    float* out = (float*)d_out;

    dim3 g1(T * B / BM, H / BN, 2);
    proj_kernel<<<g1, 256>>>(inp, Wxf, bf, Wxb, bb);

    scan_kernel<<<128, 256>>>(Whf, Whb, out);
}